// round 7
// baseline (speedup 1.0000x reference)
#include <cuda_runtime.h>

typedef unsigned long long ULL;
typedef unsigned int uint;

constexpr int B    = 512;
constexpr int T    = 2048;
constexpr int H    = 64;
constexpr int NB   = 4;       // batch elements per block
constexpr int NBLK = B / NB;  // 128 blocks
constexpr int NGT  = 256;     // gate threads
constexpr int NTHR = NGT + 64;// + 2 layer-2 warps = 320

__device__ __forceinline__ ULL pack2(float x, float y) {
    ULL r; asm("mov.b64 %0, {%1, %2};" : "=l"(r) : "f"(x), "f"(y)); return r;
}
__device__ __forceinline__ void unpack2(ULL v, float& x, float& y) {
    asm("mov.b64 {%0, %1}, %2;" : "=f"(x), "=f"(y) : "l"(v));
}
__device__ __forceinline__ ULL ffma2(ULL a, ULL b, ULL c) {
    ULL d; asm("fma.rn.f32x2 %0, %1, %2, %3;" : "=l"(d) : "l"(a), "l"(b), "l"(c)); return d;
}
__device__ __forceinline__ ULL fadd2(ULL a, ULL b) {
    ULL d; asm("add.rn.f32x2 %0, %1, %2;" : "=l"(d) : "l"(a), "l"(b)); return d;
}
__device__ __forceinline__ ULL shfl_xor_ull(ULL v, int m) {
    uint lo, hi;
    asm("mov.b64 {%0, %1}, %2;" : "=r"(lo), "=r"(hi) : "l"(v));
    lo = __shfl_xor_sync(0xffffffffu, lo, m);
    hi = __shfl_xor_sync(0xffffffffu, hi, m);
    ULL r; asm("mov.b64 %0, {%1, %2};" : "=l"(r) : "r"(lo), "r"(hi));
    return r;
}
__device__ __forceinline__ float fsigm(float x) {
    return __fdividef(1.f, 1.f + __expf(-x));
}
__device__ __forceinline__ float ftanh(float x) {
    return __fdividef(2.f, 1.f + __expf(-2.f * x)) - 1.f;
}

__global__ __launch_bounds__(NTHR, 1)
void lstm2_kernel(const float* __restrict__ x,
                  const float* __restrict__ Wih1,
                  const float* __restrict__ Whh1,
                  const float* __restrict__ bih1,
                  const float* __restrict__ bhh1,
                  const float* __restrict__ Wih2,
                  const float* __restrict__ Whh2,
                  const float* __restrict__ bih2,
                  const float* __restrict__ bhh2,
                  float* __restrict__ out)
{
    __shared__ __align__(16) float xs[T][NB];        // 32KB input stage
    __shared__ __align__(16) float h2s[2][H][NB];    // double-buffered h1
    __shared__ __align__(16) float c1buf[2][H][NB];  // double-buffered c1 (layer 2)

    const int tid = threadIdx.x;
    const int b0  = blockIdx.x * NB;

    // ---- one-time preload ----
    #pragma unroll
    for (int bl = 0; bl < NB; bl++)
        for (int t = tid; t < T; t += NTHR)
            xs[t][bl] = x[(b0 + bl) * T + t];
    for (int i = tid; i < 2 * H * NB; i += NTHR)
        (&h2s[0][0][0])[i] = 0.f;

    const bool is_gate = tid < NGT;

    // gate mapping: half = tid&1 (k-half), cls = (tid>>1)&1, j = tid>>2 (unit)
    // cls0 owns gates (i, g) of unit j; cls1 owns (f, o).
    // Weight pairs packed BOTH ways so one h-load feeds both gates:
    //   {wA,wB}*{h0,h1} -> {A0,B1};  {wB,wA}*{h0,h1} -> {B0,A1}
    ULL ww_f[32], ww_r[32];
    ULL wih_f = 0, wih_r = 0, b_f = 0, b_r = 0;
    int half = 0, cls = 0, j = 0;
    float c1a = 0.f, c1b = 0.f, c1c = 0.f, c1d = 0.f;  // cls1: c state (4 batches)
    if (is_gate) {
        half = tid & 1;
        cls  = (tid >> 1) & 1;
        j    = tid >> 2;
        const int gA = (cls ? H : 0) + j;        // i or f
        const int gB = (cls ? 3 * H : 2 * H) + j;// g or o
        #pragma unroll
        for (int kk = 0; kk < 32; kk++) {
            const int k = half * 32 + kk;
            float wA = Whh1[gA * H + k];
            float wB = Whh1[gB * H + k];
            ww_f[kk] = pack2(wA, wB);
            ww_r[kk] = pack2(wB, wA);
        }
        if (!half) {  // input + bias contribution counted once (half 0)
            float wiA = Wih1[gA], wiB = Wih1[gB];
            float bA = bih1[gA] + bhh1[gA];
            float bB = bih1[gB] + bhh1[gB];
            wih_f = pack2(wiA, wiB);
            wih_r = pack2(wiB, wiA);
            b_f   = pack2(bA, bB);
            b_r   = pack2(bB, bA);
        }
    }

    // layer-2 thread state (tid in [256,320)): (bl, gate qq, k-segment of 16)
    float w2[16];
    float whh2q = 0.f, b2q = 0.f, h2v = 0.f, c2 = 0.f;
    const int l = tid - NGT;
    int bl2 = 0, ks = 0;
    if (!is_gate) {
        bl2 = l >> 4;
        const int qq = (l >> 2) & 3;
        ks = (l & 3) * 16;
        #pragma unroll
        for (int jj = 0; jj < 16; jj++) w2[jj] = Wih2[qq * H + ks + jj];
        whh2q = Whh2[qq];
        b2q   = bih2[qq] + bhh2[qq];
    }
    __syncthreads();

    for (int t = 0; t <= T; t++) {
        const int wb = t & 1;       // write buffer this step
        const int rb = wb ^ 1;      // read buffer (prev step's h)
        if (is_gate) {
            if (t < T) {
                ulonglong2 xp = *reinterpret_cast<const ulonglong2*>(&xs[t][0]);
                ULL a01  = ffma2(wih_f, xp.x, b_f);  // {A0,B1}
                ULL a01r = ffma2(wih_r, xp.x, b_r);  // {B0,A1}
                ULL a23  = ffma2(wih_f, xp.y, b_f);  // {A2,B3}
                ULL a23r = ffma2(wih_r, xp.y, b_r);  // {B2,A3}
                const int base = half * 32;
                ulonglong2 pf[4];
                #pragma unroll
                for (int i = 0; i < 4; i++)
                    pf[i] = *reinterpret_cast<const ulonglong2*>(
                        &h2s[rb][base + i][0]);
                #pragma unroll
                for (int kk = 0; kk < 32; kk++) {
                    ulonglong2 hv = pf[kk & 3];
                    if (kk + 4 < 32)
                        pf[kk & 3] = *reinterpret_cast<const ulonglong2*>(
                            &h2s[rb][base + kk + 4][0]);
                    a01  = ffma2(ww_f[kk], hv.x, a01);
                    a01r = ffma2(ww_r[kk], hv.x, a01r);
                    a23  = ffma2(ww_f[kk], hv.y, a23);
                    a23r = ffma2(ww_r[kk], hv.y, a23r);
                }
                // combine k-halves (partner lane = xor 1)
                a01  = fadd2(a01,  shfl_xor_ull(a01, 1));
                a01r = fadd2(a01r, shfl_xor_ull(a01r, 1));
                a23  = fadd2(a23,  shfl_xor_ull(a23, 1));
                a23r = fadd2(a23r, shfl_xor_ull(a23r, 1));
                float A0, A1, A2, A3, B0, B1, B2, B3;
                unpack2(a01,  A0, B1);
                unpack2(a01r, B0, A1);
                unpack2(a23,  A2, B3);
                unpack2(a23r, B2, A3);
                // activations: A (i or f) -> sigmoid; B: cls0 g -> tanh, cls1 o -> sigmoid
                A0 = fsigm(A0); A1 = fsigm(A1); A2 = fsigm(A2); A3 = fsigm(A3);
                const bool isg = (cls == 0);
                {
                    float s0 = fsigm(isg ? 2.f * B0 : B0);
                    float s1 = fsigm(isg ? 2.f * B1 : B1);
                    float s2 = fsigm(isg ? 2.f * B2 : B2);
                    float s3 = fsigm(isg ? 2.f * B3 : B3);
                    B0 = isg ? 2.f * s0 - 1.f : s0;
                    B1 = isg ? 2.f * s1 - 1.f : s1;
                    B2 = isg ? 2.f * s2 - 1.f : s2;
                    B3 = isg ? 2.f * s3 - 1.f : s3;
                }
                // cls0 sends p[b] = sigm(i)*tanh(g); cls1 (owner of c) updates
                float p0 = A0 * B0, p1 = A1 * B1, p2 = A2 * B2, p3 = A3 * B3;
                p0 = __shfl_xor_sync(0xffffffffu, p0, 2);
                p1 = __shfl_xor_sync(0xffffffffu, p1, 2);
                p2 = __shfl_xor_sync(0xffffffffu, p2, 2);
                p3 = __shfl_xor_sync(0xffffffffu, p3, 2);
                if (cls) {
                    c1a = fmaf(A0, c1a, p0);   // f*c + i*g
                    c1b = fmaf(A1, c1b, p1);
                    c1c = fmaf(A2, c1c, p2);
                    c1d = fmaf(A3, c1d, p3);
                    if (!half) {               // store h
                        *reinterpret_cast<float4*>(&h2s[wb][j][0]) =
                            make_float4(B0 * ftanh(c1a), B1 * ftanh(c1b),
                                        B2 * ftanh(c1c), B3 * ftanh(c1d));
                    } else {                   // store c1 for layer 2
                        *reinterpret_cast<float4*>(&c1buf[wb][j][0]) =
                            make_float4(c1a, c1b, c1c, c1d);
                    }
                }
            }
        } else if (t > 0) {
            // layer 2 consumes c1 of step t-1 (one step behind)
            const float* cb = &c1buf[(t + 1) & 1][0][0];
            float s = 0.f;
            #pragma unroll
            for (int jj = 0; jj < 16; jj++)
                s = fmaf(cb[(ks + jj) * NB + bl2], w2[jj], s);
            s += __shfl_xor_sync(0xffffffffu, s, 1);
            s += __shfl_xor_sync(0xffffffffu, s, 2);
            const float gate = s + b2q + h2v * whh2q;
            const int lane = l & 31;
            const int base = lane & 16;
            const float gi = __shfl_sync(0xffffffffu, gate, base + 0);
            const float gf = __shfl_sync(0xffffffffu, gate, base + 4);
            const float gg = __shfl_sync(0xffffffffu, gate, base + 8);
            const float go = __shfl_sync(0xffffffffu, gate, base + 12);
            c2  = fsigm(gf) * c2 + fsigm(gi) * ftanh(gg);
            h2v = fsigm(go) * ftanh(c2);
            if ((lane & 15) == 0)
                out[(b0 + bl2) * T + (t - 1)] = c2;
        }
        __syncthreads();  // single barrier per step
    }
}

extern "C" void kernel_launch(void* const* d_in, const int* in_sizes, int n_in,
                              void* d_out, int out_size) {
    (void)in_sizes; (void)n_in; (void)out_size;
    lstm2_kernel<<<NBLK, NTHR>>>(
        (const float*)d_in[0],  // x
        (const float*)d_in[1],  // Wih1
        (const float*)d_in[2],  // Whh1
        (const float*)d_in[3],  // bih1
        (const float*)d_in[4],  // bhh1
        (const float*)d_in[5],  // Wih2
        (const float*)d_in[6],  // Whh2
        (const float*)d_in[7],  // bih2
        (const float*)d_in[8],  // bhh2
        (float*)d_out);
}